// round 7
// baseline (speedup 1.0000x reference)
#include <cuda_runtime.h>

// ---------------------------------------------------------------------------
// ImprovedAILayerNorm: int8-quantized layernorm with LUT integer sqrt.
// R7: ONE persistent kernel (148 blocks x 1024 thr, all co-resident) with a
// software grid barrier between phases. Each warp owns fixed 4KB chunks and
// re-reads them every phase -> per-SM ~900KB working set stays in L2.
//   phase1 : chunk min/max stores + global absmax (+ block0: g/b const check)
//   phase2a: chunk int sums (q, q^2) stores
//   phase2b: thread-per-row stats (exact int combine) + global ymax
//   phase3 : quantize + write (ldcs/stcs)
// No cross-launch gaps, no per-pass cold starts.
// ---------------------------------------------------------------------------

#define NBLOCKS 148
#define NTHREADS 1024
#define NWARPS (NBLOCKS * (NTHREADS / 32))      // 4736
#define CHUNK 1024                               // elements per chunk (4KB)
#define MAX_ROWS 32768
#define MAX_CHUNKS 131072

__device__ int      g_absmax_bits;
__device__ int      g_ymax_bits;
__device__ int      g_const_flag;
__device__ float    g_g0, g_b0;
__device__ float    g_cmin[MAX_CHUNKS];
__device__ float    g_cmax[MAX_CHUNKS];
__device__ int      g_cisum[MAX_CHUNKS];
__device__ int      g_cisum2[MAX_CHUNKS];
__device__ float    g_mu[MAX_ROWS];
__device__ float    g_inv_std[MAX_ROWS];
__device__ unsigned g_arrive;                    // zero-init; returns to 0
__device__ volatile unsigned g_gen;

// ---------------------------------------------------------------------------
__device__ __forceinline__ void grid_barrier() {
    __syncthreads();
    if (threadIdx.x == 0) {
        __threadfence();
        unsigned gen = g_gen;
        if (atomicAdd(&g_arrive, 1u) == (unsigned)(NBLOCKS - 1)) {
            g_arrive = 0;
            __threadfence();
            g_gen = gen + 1;
        } else {
            while (g_gen == gen) __nanosleep(64);
        }
        __threadfence();
    }
    __syncthreads();
}

// ordered-uint mapping for float min/max warp redux
__device__ __forceinline__ unsigned f2ord(float f) {
    unsigned u = __float_as_uint(f);
    return (u & 0x80000000u) ? ~u : (u | 0x80000000u);
}
__device__ __forceinline__ float ord2f(unsigned u) {
    return __uint_as_float((u & 0x80000000u) ? (u & 0x7fffffffu) : ~u);
}

// Exact replica of reference sqrt_rounded_vec (LUT-based rounded int sqrt)
__device__ __forceinline__ float sqrt_rounded(int d) {
    int msb = 31 - __clz(d);
    int k   = msb >> 1;
    int dn  = d << ((7 - k) * 2);
    int addr = (dn >> 8) & 255;
    int v    = addr * 256 + 128;
    int mant = (int)sqrtf((float)v);
    if (mant * mant > v) mant--;
    if ((mant + 1) * (mant + 1) <= v) mant++;
    int qf = mant >> (7 - k);
    int boundary = qf * qf + qf;
    return (float)((d > boundary) ? qf + 1 : qf);
}

// ---------------------------------------------------------------------------
__global__ void __launch_bounds__(NTHREADS)
k_persist(const float* __restrict__ x,
          const float* __restrict__ gamma,
          const float* __restrict__ beta,
          float* __restrict__ out,
          int N, int rows) {
    const int lane = threadIdx.x & 31;
    const int gw   = (blockIdx.x * NTHREADS + threadIdx.x) >> 5;   // 0..4735
    const int cpr  = N / CHUNK;                                    // 4
    const int nchunks = rows * cpr;

    // ---- block 0, warp 0: init + gamma/beta const check (pre-B1) ----
    if (blockIdx.x == 0 && threadIdx.x < 32) {
        if (lane == 0) {
            g_absmax_bits = 0;
            g_ymax_bits   = 0;
            g_g0 = gamma[0];
            g_b0 = beta[0];
        }
        __syncwarp();
        float g0 = g_g0, b0 = g_b0;
        bool bad = false;
        for (int i = lane; i < N; i += 32)
            bad |= (gamma[i] != g0) || (beta[i] != b0);
        bad = __any_sync(0xffffffffu, bad);
        if (lane == 0) g_const_flag = bad ? 0 : 1;
    }

    // ================= phase 1: chunk min/max + global absmax =============
    {
        float wam = 0.0f;                                // warp-local absmax
        for (int c = gw; c < nchunks; c += NWARPS) {
            const float4* p = reinterpret_cast<const float4*>(x + (size_t)c * CHUNK);
            float mn = 3.4e38f, mx = -3.4e38f;
            #pragma unroll
            for (int j = 0; j < CHUNK / 128; j++) {      // 8 iters
                float4 v = p[j * 32 + lane];
                mn = fminf(mn, fminf(fminf(v.x, v.y), fminf(v.z, v.w)));
                mx = fmaxf(mx, fmaxf(fmaxf(v.x, v.y), fmaxf(v.z, v.w)));
            }
            unsigned umx = __reduce_max_sync(0xffffffffu, f2ord(mx));
            unsigned umn = __reduce_min_sync(0xffffffffu, f2ord(mn));
            if (lane == 0) {
                float fmx = ord2f(umx), fmn = ord2f(umn);
                g_cmin[c] = fmn;
                g_cmax[c] = fmx;
                wam = fmaxf(wam, fmaxf(fabsf(fmn), fabsf(fmx)));
            }
        }
        if (lane == 0 && wam > 0.0f)
            atomicMax(&g_absmax_bits, (int)__float_as_uint(wam));
    }
    grid_barrier();   // B1: absmax + const_flag final

    // ================= phase 2a: chunk integer moments =====================
    const float s     = fmaxf(__int_as_float(g_absmax_bits) / 127.0f, 1e-8f);
    const float inv_s = 1.0f / s;
    {
        for (int c = gw; c < nchunks; c += NWARPS) {
            const float4* p = reinterpret_cast<const float4*>(x + (size_t)c * CHUNK);
            int isum = 0, isum2 = 0;
            #pragma unroll
            for (int j = 0; j < CHUNK / 128; j++) {
                float4 v = p[j * 32 + lane];
                #pragma unroll
                for (int k = 0; k < 4; k++) {
                    int q = __float2int_rn((&v.x)[k] * inv_s);   // RN half-even
                    isum  += q;
                    isum2 += q * q;
                }
            }
            isum  = __reduce_add_sync(0xffffffffu, isum);
            isum2 = __reduce_add_sync(0xffffffffu, isum2);
            if (lane == 0) {
                g_cisum[c]  = isum;
                g_cisum2[c] = isum2;
            }
        }
    }
    grid_barrier();   // B2: all chunk sums visible

    // ================= phase 2b: per-row stats + ymax ======================
    const bool cst = (g_const_flag != 0);
    if (cst) {
        // one thread per row
        float ylocal = 0.0f;
        const float g0 = g_g0, b0 = g_b0;
        for (int r = blockIdx.x * NTHREADS + threadIdx.x; r < rows;
             r += NBLOCKS * NTHREADS) {
            int t = 0, t2 = 0;
            float mn = 3.4e38f, mx = -3.4e38f;
            for (int i = 0; i < cpr; i++) {
                t  += g_cisum [r * cpr + i];
                t2 += g_cisum2[r * cpr + i];
                mn = fminf(mn, g_cmin[r * cpr + i]);
                mx = fmaxf(mx, g_cmax[r * cpr + i]);
            }
            float Ex  = (float)t  * s;
            float Ex2 = (float)t2 * (s * s);
            float mu  = Ex / (float)N;
            float var = fmaxf(Ex2 / (float)N - mu * mu, 0.0f);
            float vi  = fminf(fmaxf(rintf(var), 1.0f), 65535.0f);
            float inv = 1.0f / fmaxf(sqrt_rounded((int)vi), 1e-5f);
            g_mu[r] = mu;
            g_inv_std[r] = inv;
            float y1 = fabsf((mx - mu) * inv * g0 + b0);
            float y2 = fabsf((mn - mu) * inv * g0 + b0);
            ylocal = fmaxf(ylocal, fmaxf(y1, y2));
        }
        unsigned yb = __reduce_max_sync(0xffffffffu, __float_as_uint(ylocal));
        if (lane == 0 && yb) atomicMax(&g_ymax_bits, (int)yb);
    } else {
        // warp per row: stats from sums, then sweep row for max|y|
        float ylocal = 0.0f;
        for (int r = gw; r < rows; r += NWARPS) {
            float mu, inv;
            if (lane == 0) {
                int t = 0, t2 = 0;
                for (int i = 0; i < cpr; i++) {
                    t  += g_cisum [r * cpr + i];
                    t2 += g_cisum2[r * cpr + i];
                }
                float Ex  = (float)t  * s;
                float Ex2 = (float)t2 * (s * s);
                mu  = Ex / (float)N;
                float var = fmaxf(Ex2 / (float)N - mu * mu, 0.0f);
                float vi  = fminf(fmaxf(rintf(var), 1.0f), 65535.0f);
                inv = 1.0f / fmaxf(sqrt_rounded((int)vi), 1e-5f);
                g_mu[r] = mu;
                g_inv_std[r] = inv;
            }
            mu  = __shfl_sync(0xffffffffu, mu, 0);
            inv = __shfl_sync(0xffffffffu, inv, 0);
            const float4* xr = reinterpret_cast<const float4*>(x + (size_t)r * N);
            const float4* g4 = reinterpret_cast<const float4*>(gamma);
            const float4* b4 = reinterpret_cast<const float4*>(beta);
            for (int j = lane; j < N / 4; j += 32) {
                float4 v = xr[j];
                float4 g = g4[j];
                float4 b = b4[j];
                #pragma unroll
                for (int k = 0; k < 4; k++) {
                    float y = ((&v.x)[k] - mu) * inv * (&g.x)[k] + (&b.x)[k];
                    ylocal = fmaxf(ylocal, fabsf(y));
                }
            }
        }
        unsigned yb = __reduce_max_sync(0xffffffffu, __float_as_uint(ylocal));
        if (lane == 0 && yb) atomicMax(&g_ymax_bits, (int)yb);
    }
    grid_barrier();   // B3: ymax final

    // ================= phase 3: quantize + write ===========================
    const float so     = fmaxf(__int_as_float(g_ymax_bits) / 127.0f, 1e-8f);
    const float inv_so = 1.0f / so;

    if (cst) {
        const float g0 = g_g0, b0 = g_b0;
        for (int c = gw; c < nchunks; c += NWARPS) {
            const int row = c / cpr;
            const float4* p = reinterpret_cast<const float4*>(x + (size_t)c * CHUNK);
            float4* po = reinterpret_cast<float4*>(out + (size_t)c * CHUNK);
            const float is = g_inv_std[row];
            const float mu = g_mu[row];
            const float A2 = is * g0 * inv_so;
            const float B2 = (b0 - mu * is * g0) * inv_so;
            #pragma unroll
            for (int j = 0; j < CHUNK / 128; j++) {
                float4 v = __ldcs(&p[j * 32 + lane]);
                float4 o;
                #pragma unroll
                for (int k = 0; k < 4; k++) {
                    int q = __float2int_rn(fmaf((&v.x)[k], A2, B2));
                    q = max(-127, min(127, q));     // safety vs reassoc ulp
                    (&o.x)[k] = (float)q * so;
                }
                __stcs(&po[j * 32 + lane], o);
            }
        }
    } else {
        for (int c = gw; c < nchunks; c += NWARPS) {
            const int row  = c / cpr;
            const int part = c - row * cpr;
            const float4* p  = reinterpret_cast<const float4*>(x + (size_t)c * CHUNK);
            const float4* pg = reinterpret_cast<const float4*>(gamma + part * CHUNK);
            const float4* pb = reinterpret_cast<const float4*>(beta  + part * CHUNK);
            float4* po = reinterpret_cast<float4*>(out + (size_t)c * CHUNK);
            const float is = g_inv_std[row];
            const float mu = g_mu[row];
            #pragma unroll
            for (int j = 0; j < CHUNK / 128; j++) {
                float4 v = __ldcs(&p[j * 32 + lane]);
                float4 g = pg[j * 32 + lane];
                float4 b = pb[j * 32 + lane];
                float4 o;
                #pragma unroll
                for (int k = 0; k < 4; k++) {
                    float y = ((&v.x)[k] - mu) * is * (&g.x)[k] + (&b.x)[k];
                    int q = __float2int_rn(y * inv_so);
                    (&o.x)[k] = (float)q * so;
                }
                __stcs(&po[j * 32 + lane], o);
            }
        }
    }
}

// ---------------------------------------------------------------------------
extern "C" void kernel_launch(void* const* d_in, const int* in_sizes, int n_in,
                              void* d_out, int out_size) {
    const float* x     = (const float*)d_in[0];
    const float* gamma = (const float*)d_in[1];
    const float* beta  = (const float*)d_in[2];
    float* out = (float*)d_out;

    const int N    = in_sizes[1];        // 4096
    const int n    = in_sizes[0];        // 4*2048*4096
    const int rows = n / N;              // 8192

    k_persist<<<NBLOCKS, NTHREADS>>>(x, gamma, beta, out, N, rows);
}

// round 8
// speedup vs baseline: 1.3516x; 1.3516x over previous
#include <cuda_runtime.h>

// ---------------------------------------------------------------------------
// ImprovedAILayerNorm: int8-quantized layernorm with LUT integer sqrt.
// R8: R5 structure (best) + 2 rows per block in pass1/pass2:
//  - 4 independent LDG.128 in flight per thread (MLP_p1=4),
//  - one __syncthreads amortized over 2 rows,
//  - two leader threads finalize the two rows concurrently.
// Serpentine L2 ordering kept (p1 asc, p2 desc, p3 asc), ldcs/stcs in p3.
// ---------------------------------------------------------------------------

#define T2 512
#define NWARP (T2 / 32)
#define MAX_ROWS 32768

__device__ int   g_absmax_bits;
__device__ int   g_ymax_bits;
__device__ int   g_const_flag;
__device__ float g_g0, g_b0;
__device__ float g_mu[MAX_ROWS];
__device__ float g_inv_std[MAX_ROWS];
__device__ float g_rowmin[MAX_ROWS];
__device__ float g_rowmax[MAX_ROWS];

// ---------------------------------------------------------------------------
__global__ void k_init_check(const float* __restrict__ gamma,
                             const float* __restrict__ beta, int N) {
    if (threadIdx.x == 0) {
        g_absmax_bits = 0;
        g_ymax_bits   = 0;
        g_const_flag  = 1;
        g_g0 = gamma[0];
        g_b0 = beta[0];
    }
    __syncthreads();
    float g0 = g_g0, b0 = g_b0;
    bool bad = false;
    for (int i = threadIdx.x; i < N; i += blockDim.x)
        bad |= (gamma[i] != g0) || (beta[i] != b0);
    if (__syncthreads_or(bad) && threadIdx.x == 0) g_const_flag = 0;
}

// ordered-uint mapping for float min/max redux
__device__ __forceinline__ unsigned f2ord(float f) {
    unsigned u = __float_as_uint(f);
    return (u & 0x80000000u) ? ~u : (u | 0x80000000u);
}
__device__ __forceinline__ float ord2f(unsigned u) {
    return __uint_as_float((u & 0x80000000u) ? (u & 0x7fffffffu) : ~u);
}

// ---------------------------------------------------------------------------
// Pass 1: 2 rows/block, row min/max + global absmax. ASCENDING rows.
__global__ void __launch_bounds__(T2)
k_minmax(const float* __restrict__ x, int N) {
    const int r0 = blockIdx.x * 2;
    const float4* xa = reinterpret_cast<const float4*>(x + (size_t)r0 * N);
    const float4* xb = reinterpret_cast<const float4*>(x + (size_t)(r0 + 1) * N);

    // 4 independent loads up front (MLP_p1 = 4)
    float4 a0 = xa[threadIdx.x];
    float4 a1 = xa[T2 + threadIdx.x];
    float4 b0 = xb[threadIdx.x];
    float4 b1 = xb[T2 + threadIdx.x];

    float mnA = fminf(fminf(fminf(a0.x, a0.y), fminf(a0.z, a0.w)),
                      fminf(fminf(a1.x, a1.y), fminf(a1.z, a1.w)));
    float mxA = fmaxf(fmaxf(fmaxf(a0.x, a0.y), fmaxf(a0.z, a0.w)),
                      fmaxf(fmaxf(a1.x, a1.y), fmaxf(a1.z, a1.w)));
    float mnB = fminf(fminf(fminf(b0.x, b0.y), fminf(b0.z, b0.w)),
                      fminf(fminf(b1.x, b1.y), fminf(b1.z, b1.w)));
    float mxB = fmaxf(fmaxf(fmaxf(b0.x, b0.y), fmaxf(b0.z, b0.w)),
                      fmaxf(fmaxf(b1.x, b1.y), fmaxf(b1.z, b1.w)));

    unsigned wmnA = __reduce_min_sync(0xffffffffu, f2ord(mnA));
    unsigned wmxA = __reduce_max_sync(0xffffffffu, f2ord(mxA));
    unsigned wmnB = __reduce_min_sync(0xffffffffu, f2ord(mnB));
    unsigned wmxB = __reduce_max_sync(0xffffffffu, f2ord(mxB));

    __shared__ unsigned smn[2][NWARP], smx[2][NWARP];
    const int w = threadIdx.x >> 5;
    if ((threadIdx.x & 31) == 0) {
        smn[0][w] = wmnA; smx[0][w] = wmxA;
        smn[1][w] = wmnB; smx[1][w] = wmxB;
    }
    __syncthreads();
    // two leaders finalize the two rows concurrently
    if (threadIdx.x == 0 || threadIdx.x == 32) {
        const int r = threadIdx.x >> 5;         // 0 or 1
        unsigned umn = 0xffffffffu, umx = 0u;
        #pragma unroll
        for (int i = 0; i < NWARP; i++) {
            umn = min(umn, smn[r][i]);
            umx = max(umx, smx[r][i]);
        }
        float fmn = ord2f(umn), fmx = ord2f(umx);
        g_rowmin[r0 + r] = fmn;
        g_rowmax[r0 + r] = fmx;
        float am = fmaxf(fabsf(fmn), fabsf(fmx));
        atomicMax(&g_absmax_bits, (int)__float_as_uint(am));
    }
}

// ---------------------------------------------------------------------------
// Exact replica of reference sqrt_rounded_vec (LUT-based rounded int sqrt)
__device__ __forceinline__ float sqrt_rounded(int d) {
    int msb = 31 - __clz(d);
    int k   = msb >> 1;
    int dn  = d << ((7 - k) * 2);
    int addr = (dn >> 8) & 255;
    int v    = addr * 256 + 128;
    int mant = (int)sqrtf((float)v);
    if (mant * mant > v) mant--;
    if ((mant + 1) * (mant + 1) <= v) mant++;
    int qf = mant >> (7 - k);
    int boundary = qf * qf + qf;
    return (float)((d > boundary) ? qf + 1 : qf);
}

__device__ __forceinline__ void row_finalize(int row, int t, int t2,
                                             float s, int N, bool cst) {
    float Ex  = (float)t  * s;
    float Ex2 = (float)t2 * (s * s);
    float mu  = Ex / (float)N;
    float var = fmaxf(Ex2 / (float)N - mu * mu, 0.0f);
    float vi  = fminf(fmaxf(rintf(var), 1.0f), 65535.0f);
    float inv = 1.0f / fmaxf(sqrt_rounded((int)vi), 1e-5f);
    g_mu[row] = mu;
    g_inv_std[row] = inv;
    if (cst) {
        float g0 = g_g0, b0 = g_b0;
        float y1 = fabsf((g_rowmax[row] - mu) * inv * g0 + b0);
        float y2 = fabsf((g_rowmin[row] - mu) * inv * g0 + b0);
        atomicMax(&g_ymax_bits, (int)__float_as_uint(fmaxf(y1, y2)));
    }
}

// ---------------------------------------------------------------------------
// Pass 2: 2 rows/block int moments, DESCENDING row order. No clamps
// (|x|/s <= 127 by construction of s).
__global__ void __launch_bounds__(T2)
k_rowstats(const float* __restrict__ x,
           const float* __restrict__ gamma,
           const float* __restrict__ beta,
           int N, int rows) {
    const int r0 = rows - 2 - blockIdx.x * 2;          // pair, descending
    const float4* xa = reinterpret_cast<const float4*>(x + (size_t)r0 * N);
    const float4* xb = reinterpret_cast<const float4*>(x + (size_t)(r0 + 1) * N);
    const bool cst = (g_const_flag != 0);

    const float s     = fmaxf(__int_as_float(g_absmax_bits) / 127.0f, 1e-8f);
    const float inv_s = 1.0f / s;

    // 4 independent loads up front
    float4 a0 = xa[threadIdx.x];
    float4 a1 = xa[T2 + threadIdx.x];
    float4 b0 = xb[threadIdx.x];
    float4 b1 = xb[T2 + threadIdx.x];

    int sA = 0, s2A = 0, sB = 0, s2B = 0;
    #pragma unroll
    for (int c = 0; c < 4; c++) {
        int qa0 = __float2int_rn((&a0.x)[c] * inv_s);
        int qa1 = __float2int_rn((&a1.x)[c] * inv_s);
        int qb0 = __float2int_rn((&b0.x)[c] * inv_s);
        int qb1 = __float2int_rn((&b1.x)[c] * inv_s);
        sA  += qa0 + qa1;
        s2A += qa0 * qa0 + qa1 * qa1;
        sB  += qb0 + qb1;
        s2B += qb0 * qb0 + qb1 * qb1;
    }
    sA  = __reduce_add_sync(0xffffffffu, sA);
    s2A = __reduce_add_sync(0xffffffffu, s2A);
    sB  = __reduce_add_sync(0xffffffffu, sB);
    s2B = __reduce_add_sync(0xffffffffu, s2B);

    __shared__ int sw[4][NWARP];
    const int w = threadIdx.x >> 5;
    if ((threadIdx.x & 31) == 0) {
        sw[0][w] = sA;  sw[1][w] = s2A;
        sw[2][w] = sB;  sw[3][w] = s2B;
    }
    __syncthreads();
    if (threadIdx.x == 0 || threadIdx.x == 32) {
        const int r = threadIdx.x >> 5;                // 0 or 1
        int t = 0, t2 = 0;
        #pragma unroll
        for (int i = 0; i < NWARP; i++) {
            t  += sw[2 * r][i];
            t2 += sw[2 * r + 1][i];
        }
        row_finalize(r0 + r, t, t2, s, N, cst);
    }
    if (cst) return;

    // ---- general gamma/beta path: sweep both rows for max|y| ----
    __syncthreads();
    const float4* g4 = reinterpret_cast<const float4*>(gamma);
    const float4* b4 = reinterpret_cast<const float4*>(beta);
    float ymax = 0.0f;
    #pragma unroll
    for (int r = 0; r < 2; r++) {
        const float mu = g_mu[r0 + r];
        const float is = g_inv_std[r0 + r];
        const float4* xr = r ? xb : xa;
        #pragma unroll
        for (int j = 0; j < 2; j++) {
            float4 v = xr[j * T2 + threadIdx.x];
            float4 g = g4[j * T2 + threadIdx.x];
            float4 b = b4[j * T2 + threadIdx.x];
            #pragma unroll
            for (int c = 0; c < 4; c++) {
                float y = ((&v.x)[c] - mu) * is * (&g.x)[c] + (&b.x)[c];
                ymax = fmaxf(ymax, fabsf(y));
            }
        }
    }
    unsigned yb = __reduce_max_sync(0xffffffffu, __float_as_uint(ymax));
    __shared__ unsigned sy[NWARP];
    if ((threadIdx.x & 31) == 0) sy[w] = yb;
    __syncthreads();
    if (threadIdx.x == 0) {
        unsigned v = 0;
        #pragma unroll
        for (int i = 0; i < NWARP; i++) v = max(v, sy[i]);
        atomicMax(&g_ymax_bits, (int)v);
    }
}

// ---------------------------------------------------------------------------
// Pass 3: 1 row/block, ASCENDING (rides pass-2 residency). ldcs/stcs.
__global__ void __launch_bounds__(T2)
k_quant(const float* __restrict__ x,
        const float* __restrict__ gamma,
        const float* __restrict__ beta,
        float* __restrict__ out,
        int N) {
    const int row = blockIdx.x;
    const float4* xr = reinterpret_cast<const float4*>(x + (size_t)row * N);
    float4* orow = reinterpret_cast<float4*>(out + (size_t)row * N);

    const float mu = g_mu[row];
    const float is = g_inv_std[row];
    const float so     = fmaxf(__int_as_float(g_ymax_bits) / 127.0f, 1e-8f);
    const float inv_so = 1.0f / so;

    if (g_const_flag) {
        const float g0 = g_g0, b0 = g_b0;
        const float A2 = is * g0 * inv_so;
        const float B2 = (b0 - mu * is * g0) * inv_so;
        #pragma unroll
        for (int j = 0; j < 2; j++) {
            float4 v = __ldcs(&xr[j * T2 + threadIdx.x]);
            float4 o;
            #pragma unroll
            for (int c = 0; c < 4; c++) {
                int q = __float2int_rn(fmaf((&v.x)[c], A2, B2));
                q = max(-127, min(127, q));        // safety vs reassoc ulp
                (&o.x)[c] = (float)q * so;
            }
            __stcs(&orow[j * T2 + threadIdx.x], o);
        }
        return;
    }

    const float4* g4 = reinterpret_cast<const float4*>(gamma);
    const float4* b4 = reinterpret_cast<const float4*>(beta);
    #pragma unroll
    for (int j = 0; j < 2; j++) {
        float4 v = __ldcs(&xr[j * T2 + threadIdx.x]);
        float4 g = g4[j * T2 + threadIdx.x];
        float4 b = b4[j * T2 + threadIdx.x];
        float4 o;
        #pragma unroll
        for (int c = 0; c < 4; c++) {
            float y = ((&v.x)[c] - mu) * is * (&g.x)[c] + (&b.x)[c];
            int q = __float2int_rn(y * inv_so);
            (&o.x)[c] = (float)q * so;
        }
        __stcs(&orow[j * T2 + threadIdx.x], o);
    }
}

// ---------------------------------------------------------------------------
extern "C" void kernel_launch(void* const* d_in, const int* in_sizes, int n_in,
                              void* d_out, int out_size) {
    const float* x     = (const float*)d_in[0];
    const float* gamma = (const float*)d_in[1];
    const float* beta  = (const float*)d_in[2];
    float* out = (float*)d_out;

    const int N    = in_sizes[1];        // 4096
    const int n    = in_sizes[0];        // 4*2048*4096
    const int rows = n / N;              // 8192

    k_init_check<<<1, T2>>>(gamma, beta, N);
    k_minmax<<<rows / 2, T2>>>(x, N);
    k_rowstats<<<rows / 2, T2>>>(x, gamma, beta, N, rows);
    k_quant<<<rows, T2>>>(x, gamma, beta, out, N);
}

// round 9
// speedup vs baseline: 1.4101x; 1.0432x over previous
#include <cuda_runtime.h>

// ---------------------------------------------------------------------------
// ImprovedAILayerNorm: int8-quantized layernorm with LUT integer sqrt.
// R9 = R8 (2 rows/block reduction passes, serpentine L2, ldcs/stcs) + PDL:
// every kernel issues griddepcontrol.launch_dependents at entry, preloads its
// x data (independent of producer results), THEN griddepcontrol.wait before
// touching producer-written globals. Consumer ramp overlaps producer drain.
// ---------------------------------------------------------------------------

#define T2 512
#define NWARP (T2 / 32)
#define MAX_ROWS 32768

__device__ int   g_absmax_bits;
__device__ int   g_ymax_bits;
__device__ int   g_const_flag;
__device__ float g_g0, g_b0;
__device__ float g_mu[MAX_ROWS];
__device__ float g_inv_std[MAX_ROWS];
__device__ float g_rowmin[MAX_ROWS];
__device__ float g_rowmax[MAX_ROWS];

__device__ __forceinline__ void pdl_launch_dependents() {
    asm volatile("griddepcontrol.launch_dependents;" ::: "memory");
}
__device__ __forceinline__ void pdl_wait() {
    asm volatile("griddepcontrol.wait;" ::: "memory");
}

// ---------------------------------------------------------------------------
__global__ void k_init_check(const float* __restrict__ gamma,
                             const float* __restrict__ beta, int N) {
    pdl_launch_dependents();
    if (threadIdx.x == 0) {
        g_absmax_bits = 0;
        g_ymax_bits   = 0;
        g_const_flag  = 1;
        g_g0 = gamma[0];
        g_b0 = beta[0];
    }
    __syncthreads();
    float g0 = g_g0, b0 = g_b0;
    bool bad = false;
    for (int i = threadIdx.x; i < N; i += blockDim.x)
        bad |= (gamma[i] != g0) || (beta[i] != b0);
    if (__syncthreads_or(bad) && threadIdx.x == 0) g_const_flag = 0;
}

// ordered-uint mapping for float min/max redux
__device__ __forceinline__ unsigned f2ord(float f) {
    unsigned u = __float_as_uint(f);
    return (u & 0x80000000u) ? ~u : (u | 0x80000000u);
}
__device__ __forceinline__ float ord2f(unsigned u) {
    return __uint_as_float((u & 0x80000000u) ? (u & 0x7fffffffu) : ~u);
}

// ---------------------------------------------------------------------------
// Pass 1: 2 rows/block, row min/max + global absmax. ASCENDING rows.
// Needs producer (init) only for zeroed g_absmax_bits -> wait before atomic.
__global__ void __launch_bounds__(T2)
k_minmax(const float* __restrict__ x, int N) {
    pdl_launch_dependents();
    const int r0 = blockIdx.x * 2;
    const float4* xa = reinterpret_cast<const float4*>(x + (size_t)r0 * N);
    const float4* xb = reinterpret_cast<const float4*>(x + (size_t)(r0 + 1) * N);

    // 4 independent loads up front (MLP_p1 = 4)
    float4 a0 = xa[threadIdx.x];
    float4 a1 = xa[T2 + threadIdx.x];
    float4 b0 = xb[threadIdx.x];
    float4 b1 = xb[T2 + threadIdx.x];

    float mnA = fminf(fminf(fminf(a0.x, a0.y), fminf(a0.z, a0.w)),
                      fminf(fminf(a1.x, a1.y), fminf(a1.z, a1.w)));
    float mxA = fmaxf(fmaxf(fmaxf(a0.x, a0.y), fmaxf(a0.z, a0.w)),
                      fmaxf(fmaxf(a1.x, a1.y), fmaxf(a1.z, a1.w)));
    float mnB = fminf(fminf(fminf(b0.x, b0.y), fminf(b0.z, b0.w)),
                      fminf(fminf(b1.x, b1.y), fminf(b1.z, b1.w)));
    float mxB = fmaxf(fmaxf(fmaxf(b0.x, b0.y), fmaxf(b0.z, b0.w)),
                      fmaxf(fmaxf(b1.x, b1.y), fmaxf(b1.z, b1.w)));

    unsigned wmnA = __reduce_min_sync(0xffffffffu, f2ord(mnA));
    unsigned wmxA = __reduce_max_sync(0xffffffffu, f2ord(mxA));
    unsigned wmnB = __reduce_min_sync(0xffffffffu, f2ord(mnB));
    unsigned wmxB = __reduce_max_sync(0xffffffffu, f2ord(mxB));

    __shared__ unsigned smn[2][NWARP], smx[2][NWARP];
    const int w = threadIdx.x >> 5;
    if ((threadIdx.x & 31) == 0) {
        smn[0][w] = wmnA; smx[0][w] = wmxA;
        smn[1][w] = wmnB; smx[1][w] = wmxB;
    }
    __syncthreads();
    if (threadIdx.x == 0 || threadIdx.x == 32) {
        const int r = threadIdx.x >> 5;         // 0 or 1
        unsigned umn = 0xffffffffu, umx = 0u;
        #pragma unroll
        for (int i = 0; i < NWARP; i++) {
            umn = min(umn, smn[r][i]);
            umx = max(umx, smx[r][i]);
        }
        float fmn = ord2f(umn), fmx = ord2f(umx);
        g_rowmin[r0 + r] = fmn;
        g_rowmax[r0 + r] = fmx;
        float am = fmaxf(fabsf(fmn), fabsf(fmx));
        pdl_wait();                              // init's zeroing visible
        atomicMax(&g_absmax_bits, (int)__float_as_uint(am));
    }
}

// ---------------------------------------------------------------------------
// Exact replica of reference sqrt_rounded_vec (LUT-based rounded int sqrt)
__device__ __forceinline__ float sqrt_rounded(int d) {
    int msb = 31 - __clz(d);
    int k   = msb >> 1;
    int dn  = d << ((7 - k) * 2);
    int addr = (dn >> 8) & 255;
    int v    = addr * 256 + 128;
    int mant = (int)sqrtf((float)v);
    if (mant * mant > v) mant--;
    if ((mant + 1) * (mant + 1) <= v) mant++;
    int qf = mant >> (7 - k);
    int boundary = qf * qf + qf;
    return (float)((d > boundary) ? qf + 1 : qf);
}

__device__ __forceinline__ void row_finalize(int row, int t, int t2,
                                             float s, int N, bool cst) {
    float Ex  = (float)t  * s;
    float Ex2 = (float)t2 * (s * s);
    float mu  = Ex / (float)N;
    float var = fmaxf(Ex2 / (float)N - mu * mu, 0.0f);
    float vi  = fminf(fmaxf(rintf(var), 1.0f), 65535.0f);
    float inv = 1.0f / fmaxf(sqrt_rounded((int)vi), 1e-5f);
    g_mu[row] = mu;
    g_inv_std[row] = inv;
    if (cst) {
        float g0 = g_g0, b0 = g_b0;
        float y1 = fabsf((g_rowmax[row] - mu) * inv * g0 + b0);
        float y2 = fabsf((g_rowmin[row] - mu) * inv * g0 + b0);
        atomicMax(&g_ymax_bits, (int)__float_as_uint(fmaxf(y1, y2)));
    }
}

// ---------------------------------------------------------------------------
// Pass 2: 2 rows/block int moments, DESCENDING row order. No clamps
// (|x|/s <= 127 by construction of s). x preloaded before pdl_wait.
__global__ void __launch_bounds__(T2)
k_rowstats(const float* __restrict__ x,
           const float* __restrict__ gamma,
           const float* __restrict__ beta,
           int N, int rows) {
    pdl_launch_dependents();
    const int r0 = rows - 2 - blockIdx.x * 2;          // pair, descending
    const float4* xa = reinterpret_cast<const float4*>(x + (size_t)r0 * N);
    const float4* xb = reinterpret_cast<const float4*>(x + (size_t)(r0 + 1) * N);

    // preload x (independent of producer results)
    float4 a0 = xa[threadIdx.x];
    float4 a1 = xa[T2 + threadIdx.x];
    float4 b0 = xb[threadIdx.x];
    float4 b1 = xb[T2 + threadIdx.x];

    pdl_wait();                                        // absmax/flag final
    const bool cst = (g_const_flag != 0);
    const float s     = fmaxf(__int_as_float(g_absmax_bits) / 127.0f, 1e-8f);
    const float inv_s = 1.0f / s;

    int sA = 0, s2A = 0, sB = 0, s2B = 0;
    #pragma unroll
    for (int c = 0; c < 4; c++) {
        int qa0 = __float2int_rn((&a0.x)[c] * inv_s);
        int qa1 = __float2int_rn((&a1.x)[c] * inv_s);
        int qb0 = __float2int_rn((&b0.x)[c] * inv_s);
        int qb1 = __float2int_rn((&b1.x)[c] * inv_s);
        sA  += qa0 + qa1;
        s2A += qa0 * qa0 + qa1 * qa1;
        sB  += qb0 + qb1;
        s2B += qb0 * qb0 + qb1 * qb1;
    }
    sA  = __reduce_add_sync(0xffffffffu, sA);
    s2A = __reduce_add_sync(0xffffffffu, s2A);
    sB  = __reduce_add_sync(0xffffffffu, sB);
    s2B = __reduce_add_sync(0xffffffffu, s2B);

    __shared__ int sw[4][NWARP];
    const int w = threadIdx.x >> 5;
    if ((threadIdx.x & 31) == 0) {
        sw[0][w] = sA;  sw[1][w] = s2A;
        sw[2][w] = sB;  sw[3][w] = s2B;
    }
    __syncthreads();
    if (threadIdx.x == 0 || threadIdx.x == 32) {
        const int r = threadIdx.x >> 5;                // 0 or 1
        int t = 0, t2 = 0;
        #pragma unroll
        for (int i = 0; i < NWARP; i++) {
            t  += sw[2 * r][i];
            t2 += sw[2 * r + 1][i];
        }
        row_finalize(r0 + r, t, t2, s, N, cst);
    }
    if (cst) return;

    // ---- general gamma/beta path: sweep both rows for max|y| ----
    __syncthreads();
    const float4* g4 = reinterpret_cast<const float4*>(gamma);
    const float4* b4 = reinterpret_cast<const float4*>(beta);
    float ymax = 0.0f;
    #pragma unroll
    for (int r = 0; r < 2; r++) {
        const float mu = g_mu[r0 + r];
        const float is = g_inv_std[r0 + r];
        const float4* xr = r ? xb : xa;
        #pragma unroll
        for (int j = 0; j < 2; j++) {
            float4 v = xr[j * T2 + threadIdx.x];
            float4 g = g4[j * T2 + threadIdx.x];
            float4 b = b4[j * T2 + threadIdx.x];
            #pragma unroll
            for (int c = 0; c < 4; c++) {
                float y = ((&v.x)[c] - mu) * is * (&g.x)[c] + (&b.x)[c];
                ymax = fmaxf(ymax, fabsf(y));
            }
        }
    }
    unsigned yb = __reduce_max_sync(0xffffffffu, __float_as_uint(ymax));
    __shared__ unsigned sy[NWARP];
    if ((threadIdx.x & 31) == 0) sy[w] = yb;
    __syncthreads();
    if (threadIdx.x == 0) {
        unsigned v = 0;
        #pragma unroll
        for (int i = 0; i < NWARP; i++) v = max(v, sy[i]);
        atomicMax(&g_ymax_bits, (int)v);
    }
}

// ---------------------------------------------------------------------------
// Pass 3: 1 row/block, ASCENDING (rides pass-2 residency). ldcs/stcs.
// x preloaded before pdl_wait.
__global__ void __launch_bounds__(T2)
k_quant(const float* __restrict__ x,
        const float* __restrict__ gamma,
        const float* __restrict__ beta,
        float* __restrict__ out,
        int N) {
    const int row = blockIdx.x;
    const float4* xr = reinterpret_cast<const float4*>(x + (size_t)row * N);
    float4* orow = reinterpret_cast<float4*>(out + (size_t)row * N);

    // preload x (independent of producer results)
    float4 v0 = __ldcs(&xr[threadIdx.x]);
    float4 v1 = __ldcs(&xr[T2 + threadIdx.x]);

    pdl_wait();                                        // mu/inv_std/ymax final
    const float mu = g_mu[row];
    const float is = g_inv_std[row];
    const float so     = fmaxf(__int_as_float(g_ymax_bits) / 127.0f, 1e-8f);
    const float inv_so = 1.0f / so;

    if (g_const_flag) {
        const float g0 = g_g0, b0 = g_b0;
        const float A2 = is * g0 * inv_so;
        const float B2 = (b0 - mu * is * g0) * inv_so;
        float4 o0, o1;
        #pragma unroll
        for (int c = 0; c < 4; c++) {
            int q0 = __float2int_rn(fmaf((&v0.x)[c], A2, B2));
            int q1 = __float2int_rn(fmaf((&v1.x)[c], A2, B2));
            q0 = max(-127, min(127, q0));              // safety vs reassoc ulp
            q1 = max(-127, min(127, q1));
            (&o0.x)[c] = (float)q0 * so;
            (&o1.x)[c] = (float)q1 * so;
        }
        __stcs(&orow[threadIdx.x], o0);
        __stcs(&orow[T2 + threadIdx.x], o1);
        return;
    }

    const float4* g4 = reinterpret_cast<const float4*>(gamma);
    const float4* b4 = reinterpret_cast<const float4*>(beta);
    float4 ga = g4[threadIdx.x], gb = g4[T2 + threadIdx.x];
    float4 ba = b4[threadIdx.x], bb = b4[T2 + threadIdx.x];
    float4 o0, o1;
    #pragma unroll
    for (int c = 0; c < 4; c++) {
        float y0 = ((&v0.x)[c] - mu) * is * (&ga.x)[c] + (&ba.x)[c];
        float y1 = ((&v1.x)[c] - mu) * is * (&gb.x)[c] + (&bb.x)[c];
        (&o0.x)[c] = (float)__float2int_rn(y0 * inv_so) * so;
        (&o1.x)[c] = (float)__float2int_rn(y1 * inv_so) * so;
    }
    __stcs(&orow[threadIdx.x], o0);
    __stcs(&orow[T2 + threadIdx.x], o1);
}

// ---------------------------------------------------------------------------
static void launch_pdl(void* func, dim3 grid, dim3 block, void** args) {
    cudaLaunchConfig_t cfg = {};
    cfg.gridDim = grid;
    cfg.blockDim = block;
    cfg.stream = 0;
    cudaLaunchAttribute attr[1];
    attr[0].id = cudaLaunchAttributeProgrammaticStreamSerialization;
    attr[0].val.programmaticStreamSerializationAllowed = 1;
    cfg.attrs = attr;
    cfg.numAttrs = 1;
    cudaLaunchKernelExC(&cfg, func, args);
}

extern "C" void kernel_launch(void* const* d_in, const int* in_sizes, int n_in,
                              void* d_out, int out_size) {
    const float* x     = (const float*)d_in[0];
    const float* gamma = (const float*)d_in[1];
    const float* beta  = (const float*)d_in[2];
    float* out = (float*)d_out;

    int N    = in_sizes[1];              // 4096
    const int n = in_sizes[0];           // 4*2048*4096
    int rows = n / N;                    // 8192

    {   // init+check (plain launch)
        void* args[] = {(void*)&gamma, (void*)&beta, (void*)&N};
        cudaLaunchConfig_t cfg = {};
        cfg.gridDim = dim3(1); cfg.blockDim = dim3(T2); cfg.stream = 0;
        cudaLaunchKernelExC(&cfg, (void*)k_init_check, args);
    }
    {   // pass 1 (PDL after init)
        void* args[] = {(void*)&x, (void*)&N};
        launch_pdl((void*)k_minmax, dim3(rows / 2), dim3(T2), args);
    }
    {   // pass 2 (PDL after pass 1)
        void* args[] = {(void*)&x, (void*)&gamma, (void*)&beta,
                        (void*)&N, (void*)&rows};
        launch_pdl((void*)k_rowstats, dim3(rows / 2), dim3(T2), args);
    }
    {   // pass 3 (PDL after pass 2)
        void* args[] = {(void*)&x, (void*)&gamma, (void*)&beta,
                        (void*)&out, (void*)&N};
        launch_pdl((void*)k_quant, dim3(rows), dim3(T2), args);
    }
}